// round 1
// baseline (speedup 1.0000x reference)
#include <cuda_runtime.h>

#define OUT_CH 16
#define PH 7
#define PW 7
#define SR 2
#define HH 80
#define WW 80
#define NPLANE (OUT_CH * PH * PW)   // 784 channels == outputs per roi

__device__ __forceinline__ float bilinear_sample(const float* __restrict__ p,
                                                 float y, float x) {
    // mask on UNCLIPPED coords (matches reference)
    if (y < -1.0f || y > (float)HH || x < -1.0f || x > (float)WW) return 0.0f;
    float yc = fminf(fmaxf(y, 0.0f), (float)(HH - 1));
    float xc = fminf(fmaxf(x, 0.0f), (float)(WW - 1));
    int y0 = (int)floorf(yc);
    int x0 = (int)floorf(xc);
    int y1 = min(y0 + 1, HH - 1);
    int x1 = min(x0 + 1, WW - 1);
    float ly = yc - (float)y0, lx = xc - (float)x0;
    float hy = 1.0f - ly,      hx = 1.0f - lx;
    float v00 = __ldg(p + y0 * WW + x0);
    float v01 = __ldg(p + y0 * WW + x1);
    float v10 = __ldg(p + y1 * WW + x0);
    float v11 = __ldg(p + y1 * WW + x1);
    return hy * (hx * v00 + lx * v01) + ly * (hx * v10 + lx * v11);
}

__global__ void __launch_bounds__(NPLANE)
psroi_align_kernel(const float* __restrict__ feat,
                   const float* __restrict__ rois,
                   float* __restrict__ out) {
    const int n = blockIdx.x;

    __shared__ float s_x1, s_y1, s_bh, s_bw;
    __shared__ int   s_b;
    if (threadIdx.x == 0) {
        const float* r = rois + (size_t)n * 5;
        float b_f = r[0];
        float x1 = r[1] * (float)WW;
        float y1 = r[2] * (float)HH;
        float x2 = r[3] * (float)WW;
        float y2 = r[4] * (float)HH;
        float roi_h = fmaxf(y2 - y1, 0.1f);
        float roi_w = fmaxf(x2 - x1, 0.1f);
        s_b  = (int)b_f;
        s_x1 = x1;
        s_y1 = y1;
        s_bh = roi_h / (float)PH;
        s_bw = roi_w / (float)PW;
    }
    __syncthreads();

    const int idx = threadIdx.x;          // = co*49 + ph*7 + pw = channel index
    const int rem = idx % (PH * PW);
    const int ph  = rem / PW;
    const int pw  = rem % PW;

    const float bh = s_bh, bw = s_bw;
    const float ybase = s_y1 + (float)ph * bh;
    const float xbase = s_x1 + (float)pw * bw;

    const float* __restrict__ plane =
        feat + ((size_t)s_b * NPLANE + (size_t)idx) * (HH * WW);

    // SR=2 sample offsets: (s+0.5)*bin/SR for s=0,1
    float y0s = ybase + 0.25f * bh;
    float y1s = ybase + 0.75f * bh;
    float x0s = xbase + 0.25f * bw;
    float x1s = xbase + 0.75f * bw;

    float acc = bilinear_sample(plane, y0s, x0s)
              + bilinear_sample(plane, y0s, x1s)
              + bilinear_sample(plane, y1s, x0s)
              + bilinear_sample(plane, y1s, x1s);

    out[(size_t)n * NPLANE + idx] = acc * (1.0f / (SR * SR));
}

extern "C" void kernel_launch(void* const* d_in, const int* in_sizes, int n_in,
                              void* d_out, int out_size) {
    const float* feat = (const float*)d_in[0];
    const float* rois = (const float*)d_in[1];
    float* out = (float*)d_out;
    const int n_rois = in_sizes[1] / 5;   // 512
    psroi_align_kernel<<<n_rois, NPLANE>>>(feat, rois, out);
}

// round 2
// speedup vs baseline: 1.0135x; 1.0135x over previous
#include <cuda_runtime.h>

#define OUT_CH 16
#define PH 7
#define PW 7
#define SR 2
#define HH 80
#define WW 80
#define NPLANE (OUT_CH * PH * PW)   // 784 outputs per roi
#define HALF   (NPLANE / 2)         // 392 threads, ILP=2

// Branchless bilinear sample: mask on UNCLIPPED coords folded into the result
// as a float multiply; loads always issued at clamped (in-range) addresses.
__device__ __forceinline__ float sample_val(const float* __restrict__ p,
                                            float y, float x) {
    float m = (y >= -1.0f && y <= (float)HH && x >= -1.0f && x <= (float)WW)
                  ? 1.0f : 0.0f;
    float yc = fminf(fmaxf(y, 0.0f), (float)(HH - 1));
    float xc = fminf(fmaxf(x, 0.0f), (float)(WW - 1));
    int y0 = (int)floorf(yc);
    int x0 = (int)floorf(xc);
    int y1 = min(y0 + 1, HH - 1);
    int x1 = min(x0 + 1, WW - 1);
    float ly = yc - (float)y0, lx = xc - (float)x0;
    float hy = 1.0f - ly,      hx = 1.0f - lx;
    const float* r0 = p + y0 * WW;
    const float* r1 = p + y1 * WW;
    float v00 = __ldg(r0 + x0);
    float v01 = __ldg(r0 + x1);
    float v10 = __ldg(r1 + x0);
    float v11 = __ldg(r1 + x1);
    return m * (hy * (hx * v00 + lx * v01) + ly * (hx * v10 + lx * v11));
}

// One output (roi n, channel idx): avg of SR*SR=4 branchless samples.
__device__ __forceinline__ float one_output(const float* __restrict__ fbase,
                                            int idx, float x1, float y1,
                                            float bh, float bw) {
    const int rem = idx % (PH * PW);
    const int ph  = rem / PW;
    const int pw  = rem % PW;
    const float ybase = y1 + (float)ph * bh;
    const float xbase = x1 + (float)pw * bw;
    const float ya = ybase + 0.25f * bh, yb = ybase + 0.75f * bh;
    const float xa = xbase + 0.25f * bw, xb = xbase + 0.75f * bw;
    const float* plane = fbase + (size_t)idx * (HH * WW);
    float acc = sample_val(plane, ya, xa)
              + sample_val(plane, ya, xb)
              + sample_val(plane, yb, xa)
              + sample_val(plane, yb, xb);
    return acc * (1.0f / (SR * SR));
}

__global__ void __launch_bounds__(HALF)
psroi_align_kernel(const float* __restrict__ feat,
                   const float* __restrict__ rois,
                   float* __restrict__ out) {
    const int n   = blockIdx.x;
    const int tid = threadIdx.x;

    // ROI params: 5 broadcast loads per thread, L1-cached.
    const float* r = rois + (size_t)n * 5;
    const int   b  = (int)__ldg(r + 0);
    const float x1 = __ldg(r + 1) * (float)WW;
    const float y1 = __ldg(r + 2) * (float)HH;
    const float x2 = __ldg(r + 3) * (float)WW;
    const float y2 = __ldg(r + 4) * (float)HH;
    const float bh = fmaxf(y2 - y1, 0.1f) * (1.0f / (float)PH);
    const float bw = fmaxf(x2 - x1, 0.1f) * (1.0f / (float)PW);

    const float* fbase = feat + (size_t)b * NPLANE * (HH * WW);

    // ILP=2: two independent outputs per thread -> 32 LDGs in flight.
    float o0 = one_output(fbase, tid,        x1, y1, bh, bw);
    float o1 = one_output(fbase, tid + HALF, x1, y1, bh, bw);

    float* ob = out + (size_t)n * NPLANE;
    ob[tid]        = o0;
    ob[tid + HALF] = o1;
}

extern "C" void kernel_launch(void* const* d_in, const int* in_sizes, int n_in,
                              void* d_out, int out_size) {
    const float* feat = (const float*)d_in[0];
    const float* rois = (const float*)d_in[1];
    float* out = (float*)d_out;
    const int n_rois = in_sizes[1] / 5;   // 512
    psroi_align_kernel<<<n_rois, HALF>>>(feat, rois, out);
}